// round 1
// baseline (speedup 1.0000x reference)
#include <cuda_runtime.h>
#include <math.h>

typedef unsigned long long u64;

// ---------------- packed f32x2 helpers (sm_103a) ----------------
__device__ __forceinline__ u64 pack2(float a, float b){ u64 r; asm("mov.b64 %0,{%1,%2};":"=l"(r):"f"(a),"f"(b)); return r; }
__device__ __forceinline__ u64 pack1(float a){ u64 r; asm("mov.b64 %0,{%1,%1};":"=l"(r):"f"(a)); return r; }
__device__ __forceinline__ void unpack2(u64 v, float& a, float& b){ asm("mov.b64 {%0,%1},%2;":"=f"(a),"=f"(b):"l"(v)); }
__device__ __forceinline__ u64 fma2(u64 a, u64 b, u64 c){ u64 d; asm("fma.rn.f32x2 %0,%1,%2,%3;":"=l"(d):"l"(a),"l"(b),"l"(c)); return d; }
__device__ __forceinline__ u64 add2(u64 a, u64 b){ u64 d; asm("add.rn.f32x2 %0,%1,%2;":"=l"(d):"l"(a),"l"(b)); return d; }

__device__ __forceinline__ float gelu1(float v){ return 0.5f*v*(1.0f + erff(v*0.70710678118654752f)); }
__device__ __forceinline__ u64 gelu2(u64 p){ float a,b; unpack2(p,a,b); return pack2(gelu1(a), gelu1(b)); }
__device__ __forceinline__ u64 tanh2(u64 p){ float a,b; unpack2(p,a,b); return pack2(tanhf(a), tanhf(b)); }
__device__ __forceinline__ float sig1(float v){ return 1.0f/(1.0f + expf(-v)); }

// ---------------- folded-weight scratch (device globals; no allocs) ----------------
__device__ float g_A[1024];   // (wq^T wk) / sqrt(32)
__device__ float g_W1[1024];  // w_ih @ Wo @ wv
__device__ float g_r[32];     // (wk^T bq) / sqrt(32)
__device__ float g_c1[32];    // w_ih @ (Wo bv + bo) + b_ih + b_hh

// ---------------- prep kernel: fold weights once per launch ----------------
__global__ void prep_kernel(const float* __restrict__ ipw, const float* __restrict__ ipb,
                            const float* __restrict__ opw, const float* __restrict__ opb,
                            const float* __restrict__ wih, const float* __restrict__ bih,
                            const float* __restrict__ bhh)
{
    __shared__ float T[1024];   // Wo @ wv
    __shared__ float t2[32];    // Wo bv + bo
    const float inv = 0.17677669529663688f; // 1/sqrt(32)
    int tid = threadIdx.x;
    int i = tid >> 5, j = tid & 31;
    const float* wq = ipw;
    const float* wk = ipw + 1024;
    const float* wv = ipw + 2048;

    float a = 0.f, t = 0.f;
    #pragma unroll 8
    for (int m = 0; m < 32; m++){
        a += wq[m*32 + i] * wk[m*32 + j];
        t += opw[i*32 + m] * wv[m*32 + j];
    }
    g_A[i*32 + j] = a * inv;
    T[i*32 + j] = t;

    if (i == 0){
        float rr = 0.f, tt = 0.f;
        #pragma unroll 8
        for (int m = 0; m < 32; m++){
            rr += ipb[m] * wk[m*32 + j];       // bq . wk col j
            tt += opw[j*32 + m] * ipb[64 + m]; // Wo row j . bv
        }
        g_r[j] = rr * inv;
        t2[j] = tt + opb[j];
    }
    __syncthreads();

    float w1 = 0.f;
    #pragma unroll 8
    for (int m = 0; m < 32; m++)
        w1 += wih[i*32 + m] * T[m*32 + j];
    g_W1[i*32 + j] = w1;

    if (i == 0){
        float c = 0.f;
        #pragma unroll 8
        for (int m = 0; m < 32; m++)
            c += wih[j*32 + m] * t2[m];
        g_c1[j] = c + bih[j] + bhh[j];
    }
}

// ---------------- fused main kernel: one thread = two rows (f32x2-packed) ----------------
__global__ __launch_bounds__(128) void fused_kernel(
    const float* __restrict__ x,
    const float* __restrict__ embw, const float* __restrict__ embb,
    const float* __restrict__ whh,
    const float* __restrict__ decw, const float* __restrict__ decb,
    const float* __restrict__ outw, const float* __restrict__ outb,
    float* __restrict__ out, int B)
{
    // weights duplicated element-wise so ld.shared.v2.u64 returns packed (w,w) pairs
    __shared__ __align__(16) float sA [2048];
    __shared__ __align__(16) float sW1[2048];
    __shared__ __align__(16) float sWh[2048];
    __shared__ __align__(16) float sDec[320];
    __shared__ __align__(16) u64 sC1[32];
    __shared__ __align__(16) u64 sR [32];
    __shared__ __align__(16) u64 sEmbB[32];
    __shared__ float sEmb[160];
    __shared__ float sDecB[8];
    __shared__ float sOw[16];
    __shared__ float sOb[4];

    const int tid = threadIdx.x;
    for (int i = tid; i < 1024; i += 128){
        float a = g_A[i];  sA [2*i] = a; sA [2*i+1] = a;
        float b = g_W1[i]; sW1[2*i] = b; sW1[2*i+1] = b;
        float c = whh[i];  sWh[2*i] = c; sWh[2*i+1] = c;
    }
    for (int i = tid; i < 160; i += 128){
        float v = decw[i]; sDec[2*i] = v; sDec[2*i+1] = v;
        sEmb[i] = embw[i];
    }
    if (tid < 32){ sC1[tid] = pack1(g_c1[tid]); sR[tid] = pack1(g_r[tid]); sEmbB[tid] = pack1(embb[tid]); }
    if (tid < 15) sOw[tid] = outw[tid];
    if (tid < 5)  sDecB[tid] = decb[tid];
    if (tid < 3)  sOb[tid] = outb[tid];
    __syncthreads();

    long long gth = (long long)blockIdx.x * 128 + tid;
    long long r0 = 2*gth;
    if (r0 >= (long long)B) return;
    bool full = (r0 + 1 < (long long)B);
    long long r1 = full ? r0 + 1 : r0;

    // ---- load x rows r0, r1 (10 floats each); 80B per thread, 16B aligned ----
    float xa[10], xb[10];
    if (full){
        const float4* xp = reinterpret_cast<const float4*>(x + r0*10);
        float4 f0 = xp[0], f1 = xp[1], f2 = xp[2], f3 = xp[3], f4 = xp[4];
        xa[0]=f0.x; xa[1]=f0.y; xa[2]=f0.z; xa[3]=f0.w;
        xa[4]=f1.x; xa[5]=f1.y; xa[6]=f1.z; xa[7]=f1.w;
        xa[8]=f2.x; xa[9]=f2.y;
        xb[0]=f2.z; xb[1]=f2.w; xb[2]=f3.x; xb[3]=f3.y;
        xb[4]=f3.z; xb[5]=f3.w; xb[6]=f4.x; xb[7]=f4.y;
        xb[8]=f4.z; xb[9]=f4.w;
    } else {
        #pragma unroll
        for (int i = 0; i < 10; i++){ xa[i] = x[r0*10 + i]; xb[i] = xa[i]; }
    }
    u64 x0p[5], x1p[5];
    #pragma unroll
    for (int k = 0; k < 5; k++){ x0p[k] = pack2(xa[k], xb[k]); x1p[k] = pack2(xa[5+k], xb[5+k]); }

    // ---- embedding: e_s = gelu(fc_emb_w x_s + b) ; de = e1 - e0 ----
    u64 e0[32], de[32];
    #pragma unroll
    for (int l = 0; l < 32; l++){
        u64 a0 = sEmbB[l], a1 = a0;
        #pragma unroll
        for (int k = 0; k < 5; k++){
            u64 wp = pack1(sEmb[l*5 + k]);
            a0 = fma2(wp, x0p[k], a0);
            a1 = fma2(wp, x1p[k], a1);
        }
        e0[l] = gelu2(a0);
        de[l] = gelu2(a1);
    }
    const u64 NEG1 = pack1(-1.0f);
    #pragma unroll
    for (int l = 0; l < 32; l++) de[l] = fma2(e0[l], NEG1, de[l]);   // de = e1 - e0

    // ---- attention scores via w = A*de ; delta_i = e_i.w + r.de (scale pre-folded) ----
    u64 w[32];
    #pragma unroll
    for (int l = 0; l < 32; l++){
        u64 acc = 0ull;
        const ulonglong2* row = reinterpret_cast<const ulonglong2*>(sA + l*64);
        #pragma unroll
        for (int c = 0; c < 16; c++){
            ulonglong2 v = row[c];
            acc = fma2(v.x, de[2*c], acc);
            acc = fma2(v.y, de[2*c+1], acc);
        }
        w[l] = acc;
    }
    u64 dE = 0ull, dD = 0ull, dR = 0ull;
    #pragma unroll
    for (int j = 0; j < 32; j++){
        dE = fma2(e0[j], w[j], dE);
        dD = fma2(de[j], w[j], dD);
        dR = fma2(sR[j], de[j], dR);
    }
    u64 del0 = add2(dE, dR);
    u64 del1 = add2(del0, dD);
    float d0a, d0b, d1a, d1b;
    unpack2(del0, d0a, d0b);
    unpack2(del1, d1a, d1b);
    u64 a01 = pack2(sig1(d0a), sig1(d0b));   // attn[0][1]
    u64 a11 = pack2(sig1(d1a), sig1(d1b));   // attn[1][1]

    // ---- mix before matvec: m_i = e0 + a_i1 * de  (in place) ----
    #pragma unroll
    for (int j = 0; j < 32; j++){
        u64 m1 = fma2(a11, de[j], e0[j]);
        u64 m0 = fma2(a01, de[j], e0[j]);
        e0[j] = m0;   // m0
        de[j] = m1;   // m1
    }

    // ---- h1 = tanh(W1 m0 + c1) ----
    u64 h1[32];
    #pragma unroll
    for (int l = 0; l < 32; l++){
        u64 acc = sC1[l];
        const ulonglong2* row = reinterpret_cast<const ulonglong2*>(sW1 + l*64);
        #pragma unroll
        for (int c = 0; c < 16; c++){
            ulonglong2 v = row[c];
            acc = fma2(v.x, e0[2*c], acc);
            acc = fma2(v.y, e0[2*c+1], acc);
        }
        h1[l] = tanh2(acc);
    }

    // ---- h2 = tanh(W1 m1 + c1 + w_hh h1) ----
    u64 h2[32];
    #pragma unroll
    for (int l = 0; l < 32; l++){
        u64 acc = sC1[l];
        const ulonglong2* rw = reinterpret_cast<const ulonglong2*>(sW1 + l*64);
        const ulonglong2* rh = reinterpret_cast<const ulonglong2*>(sWh + l*64);
        #pragma unroll
        for (int c = 0; c < 16; c++){
            ulonglong2 vw = rw[c];
            ulonglong2 vh = rh[c];
            acc = fma2(vw.x, de[2*c],   acc);
            acc = fma2(vw.y, de[2*c+1], acc);
            acc = fma2(vh.x, h1[2*c],   acc);
            acc = fma2(vh.y, h1[2*c+1], acc);
        }
        h2[l] = tanh2(acc);
    }

    // ---- decode: d = gelu(fc_dec h2 + b) ; out = out_w d + out_b ----
    u64 dvec[5];
    #pragma unroll
    for (int j = 0; j < 5; j++){
        u64 acc = pack1(sDecB[j]);
        const ulonglong2* row = reinterpret_cast<const ulonglong2*>(sDec + j*64);
        #pragma unroll
        for (int c = 0; c < 16; c++){
            ulonglong2 v = row[c];
            acc = fma2(v.x, h2[2*c], acc);
            acc = fma2(v.y, h2[2*c+1], acc);
        }
        dvec[j] = gelu2(acc);
    }
    #pragma unroll
    for (int o = 0; o < 3; o++){
        u64 acc = pack1(sOb[o]);
        #pragma unroll
        for (int j = 0; j < 5; j++)
            acc = fma2(pack1(sOw[o*5 + j]), dvec[j], acc);
        float ra, rb;
        unpack2(acc, ra, rb);
        out[r0*3 + o] = ra;
        out[r1*3 + o] = rb;
    }
}

// ---------------- launch ----------------
extern "C" void kernel_launch(void* const* d_in, const int* in_sizes, int n_in,
                              void* d_out, int out_size)
{
    const float* x      = (const float*)d_in[0];
    const float* embw   = (const float*)d_in[1];
    const float* embb   = (const float*)d_in[2];
    const float* ipw    = (const float*)d_in[3];
    const float* ipb    = (const float*)d_in[4];
    const float* opw    = (const float*)d_in[5];
    const float* opb    = (const float*)d_in[6];
    const float* wih    = (const float*)d_in[7];
    const float* bih    = (const float*)d_in[8];
    const float* whh    = (const float*)d_in[9];
    const float* bhh    = (const float*)d_in[10];
    const float* decw   = (const float*)d_in[11];
    const float* decb   = (const float*)d_in[12];
    const float* outw   = (const float*)d_in[13];
    const float* outb   = (const float*)d_in[14];
    float* out = (float*)d_out;

    int B = in_sizes[0] / 10;

    prep_kernel<<<1, 1024>>>(ipw, ipb, opw, opb, wih, bih, bhh);

    long long nth = ((long long)B + 1) / 2;
    int blocks = (int)((nth + 127) / 128);
    fused_kernel<<<blocks, 128>>>(x, embw, embb, whh, decw, decb, outw, outb, out, B);
}

// round 2
// speedup vs baseline: 8.4277x; 8.4277x over previous
#include <cuda_runtime.h>
#include <math.h>

typedef unsigned long long u64;

// ---------------- packed f32x2 helpers (sm_103a) ----------------
__device__ __forceinline__ u64 pack2(float a, float b){ u64 r; asm("mov.b64 %0,{%1,%2};":"=l"(r):"f"(a),"f"(b)); return r; }
__device__ __forceinline__ void unpack2(u64 v, float& a, float& b){ asm("mov.b64 {%0,%1},%2;":"=f"(a),"=f"(b):"l"(v)); }
__device__ __forceinline__ u64 fma2(u64 a,u64 b,u64 c){ u64 d; asm("fma.rn.f32x2 %0,%1,%2,%3;":"=l"(d):"l"(a),"l"(b),"l"(c)); return d; }
__device__ __forceinline__ float hadd2(u64 v){ float a,b; unpack2(v,a,b); return a+b; }

// fast tanh: (e^{2x}-1)/(e^{2x}+1), 2 MUFU ops, rel err ~1e-6
__device__ __forceinline__ float tanh_fast(float x){
    float xc = fminf(fmaxf(x, -10.0f), 10.0f);
    float p = __expf(2.0f * xc);
    return __fdividef(p - 1.0f, p + 1.0f);
}
__device__ __forceinline__ float sig_fast(float x){
    return __fdividef(1.0f, 1.0f + __expf(-x));
}
__device__ __forceinline__ float gelu1(float v){ return 0.5f*v*(1.0f + erff(v*0.70710678118654752f)); }

// ---------------- folded-weight scratch (device globals; no allocs) ----------------
__device__ float g_A[1024];   // (wq^T wk) / sqrt(32)
__device__ float g_W1[1024];  // w_ih @ Wo @ wv
__device__ float g_r[32];     // (wk^T bq) / sqrt(32)
__device__ float g_c1[32];    // w_ih @ (Wo bv + bo) + b_ih + b_hh

// ---------------- prep kernel: fold weights once per launch ----------------
__global__ void prep_kernel(const float* __restrict__ ipw, const float* __restrict__ ipb,
                            const float* __restrict__ opw, const float* __restrict__ opb,
                            const float* __restrict__ wih, const float* __restrict__ bih,
                            const float* __restrict__ bhh)
{
    __shared__ float T[1024];   // Wo @ wv
    __shared__ float t2[32];    // Wo bv + bo
    const float inv = 0.17677669529663688f; // 1/sqrt(32)
    int tid = threadIdx.x;
    int i = tid >> 5, j = tid & 31;
    const float* wq = ipw;
    const float* wk = ipw + 1024;
    const float* wv = ipw + 2048;

    float a = 0.f, t = 0.f;
    #pragma unroll 8
    for (int m = 0; m < 32; m++){
        a += wq[m*32 + i] * wk[m*32 + j];
        t += opw[i*32 + m] * wv[m*32 + j];
    }
    g_A[i*32 + j] = a * inv;
    T[i*32 + j] = t;

    if (i == 0){
        float rr = 0.f, tt = 0.f;
        #pragma unroll 8
        for (int m = 0; m < 32; m++){
            rr += ipb[m] * wk[m*32 + j];       // bq . wk col j
            tt += opw[j*32 + m] * ipb[64 + m]; // Wo row j . bv
        }
        g_r[j] = rr * inv;
        t2[j] = tt + opb[j];
    }
    __syncthreads();

    float w1 = 0.f;
    #pragma unroll 8
    for (int m = 0; m < 32; m++)
        w1 += wih[i*32 + m] * T[m*32 + j];
    g_W1[i*32 + j] = w1;

    if (i == 0){
        float c = 0.f;
        #pragma unroll 8
        for (int m = 0; m < 32; m++)
            c += wih[j*32 + m] * t2[m];
        g_c1[j] = c + bih[j] + bhh[j];
    }
}

// ---------------- fused main kernel: ONE row per thread, f32x2 along reduction ----------------
__global__ __launch_bounds__(256) void fused_kernel(
    const float* __restrict__ x,
    const float* __restrict__ embw, const float* __restrict__ embb,
    const float* __restrict__ whh,
    const float* __restrict__ decw, const float* __restrict__ decb,
    const float* __restrict__ outw, const float* __restrict__ outb,
    float* __restrict__ out, int B)
{
    // natural (non-duplicated) weight layouts; pairs formed along the contraction dim
    __shared__ __align__(16) float sA [1024];
    __shared__ __align__(16) float sW1[1024];
    __shared__ __align__(16) float sWh[1024];
    __shared__ __align__(16) float sDec[160];
    __shared__ __align__(16) float sR[32];
    __shared__ float sEmb[160];
    __shared__ float sC1[32];
    __shared__ float sEmbB[32];
    __shared__ float sDecB[8];
    __shared__ float sOw[16];
    __shared__ float sOb[4];

    const int tid = threadIdx.x;
    for (int i = tid; i < 1024; i += 256){
        sA[i]  = g_A[i];
        sW1[i] = g_W1[i];
        sWh[i] = whh[i];
    }
    for (int i = tid; i < 160; i += 256){
        sDec[i] = decw[i];
        sEmb[i] = embw[i];
    }
    if (tid < 32){ sC1[tid] = g_c1[tid]; sR[tid] = g_r[tid]; sEmbB[tid] = embb[tid]; }
    if (tid < 15) sOw[tid] = outw[tid];
    if (tid < 5)  sDecB[tid] = decb[tid];
    if (tid < 3)  sOb[tid] = outb[tid];
    __syncthreads();

    int r = blockIdx.x * 256 + tid;
    if (r >= B) return;

    // ---- load x row (10 floats, 8B aligned) ----
    float xv[10];
    {
        const float2* xp = reinterpret_cast<const float2*>(x + r*10);
        #pragma unroll
        for (int k = 0; k < 5; k++){ float2 t = xp[k]; xv[2*k] = t.x; xv[2*k+1] = t.y; }
    }

    // ---- embedding: e0 = gelu(W x0 + b), de = gelu(W x1 + b) - e0, packed in l-pairs ----
    u64 e0p[16], dep[16];
    #pragma unroll
    for (int i = 0; i < 16; i++){
        int l0 = 2*i, l1 = 2*i+1;
        float a00 = sEmbB[l0], a01v = sEmbB[l0];
        float a10 = sEmbB[l1], a11v = sEmbB[l1];
        #pragma unroll
        for (int k = 0; k < 5; k++){
            float w0 = sEmb[l0*5 + k], w1 = sEmb[l1*5 + k];
            a00 = fmaf(w0, xv[k],   a00);
            a01v= fmaf(w0, xv[5+k], a01v);
            a10 = fmaf(w1, xv[k],   a10);
            a11v= fmaf(w1, xv[5+k], a11v);
        }
        float g00 = gelu1(a00), g01 = gelu1(a01v);
        float g10 = gelu1(a10), g11 = gelu1(a11v);
        e0p[i] = pack2(g00, g10);
        dep[i] = pack2(g01 - g00, g11 - g10);
    }

    // ---- attention: delta0 = e0.(A de) + r.de ; delta1 = delta0 + de.(A de) ----
    u64 dE = 0ull, dD = 0ull, dR = 0ull;
    const u64* rp = reinterpret_cast<const u64*>(sR);
    #pragma unroll
    for (int i = 0; i < 16; i++){
        const u64* rowA0 = reinterpret_cast<const u64*>(sA + (2*i)*32);
        const u64* rowA1 = reinterpret_cast<const u64*>(sA + (2*i+1)*32);
        u64 w0 = 0ull, w1 = 0ull;
        #pragma unroll
        for (int c = 0; c < 16; c++){
            w0 = fma2(rowA0[c], dep[c], w0);
            w1 = fma2(rowA1[c], dep[c], w1);
        }
        u64 wp = pack2(hadd2(w0), hadd2(w1));
        dE = fma2(e0p[i], wp, dE);
        dD = fma2(dep[i], wp, dD);
        dR = fma2(rp[i], dep[i], dR);
    }
    float d0 = hadd2(dE) + hadd2(dR);
    float d1 = d0 + hadd2(dD);
    float a01 = sig_fast(d0);   // attn[0][1]
    float a11 = sig_fast(d1);   // attn[1][1]
    u64 a01p = pack2(a01, a01);
    u64 adp  = pack2(a11 - a01, a11 - a01);

    // ---- m0 = e0 + a01*de (in place) ----
    #pragma unroll
    for (int i = 0; i < 16; i++) e0p[i] = fma2(a01p, dep[i], e0p[i]);

    // ---- h1 = tanh(W1 m0 + c1) ----
    u64 h1p[16];
    #pragma unroll
    for (int i = 0; i < 16; i++){
        const u64* r0w = reinterpret_cast<const u64*>(sW1 + (2*i)*32);
        const u64* r1w = reinterpret_cast<const u64*>(sW1 + (2*i+1)*32);
        u64 s0 = 0ull, s1 = 0ull;
        #pragma unroll
        for (int c = 0; c < 16; c++){
            s0 = fma2(r0w[c], e0p[c], s0);
            s1 = fma2(r1w[c], e0p[c], s1);
        }
        float v0 = hadd2(s0) + sC1[2*i];
        float v1 = hadd2(s1) + sC1[2*i+1];
        h1p[i] = pack2(tanh_fast(v0), tanh_fast(v1));
    }

    // ---- m1 = m0 + (a11-a01)*de (in place; de dies) ----
    #pragma unroll
    for (int i = 0; i < 16; i++) e0p[i] = fma2(adp, dep[i], e0p[i]);

    // ---- h2 = tanh(W1 m1 + Wh h1 + c1) ----
    u64 h2p[16];
    #pragma unroll
    for (int i = 0; i < 16; i++){
        const u64* rw0 = reinterpret_cast<const u64*>(sW1 + (2*i)*32);
        const u64* rw1 = reinterpret_cast<const u64*>(sW1 + (2*i+1)*32);
        const u64* rh0 = reinterpret_cast<const u64*>(sWh + (2*i)*32);
        const u64* rh1 = reinterpret_cast<const u64*>(sWh + (2*i+1)*32);
        u64 s0 = 0ull, s1 = 0ull, t0 = 0ull, t1 = 0ull;
        #pragma unroll
        for (int c = 0; c < 16; c++){
            s0 = fma2(rw0[c], e0p[c], s0);
            t0 = fma2(rh0[c], h1p[c], t0);
            s1 = fma2(rw1[c], e0p[c], s1);
            t1 = fma2(rh1[c], h1p[c], t1);
        }
        float v0 = hadd2(s0) + hadd2(t0) + sC1[2*i];
        float v1 = hadd2(s1) + hadd2(t1) + sC1[2*i+1];
        h2p[i] = pack2(tanh_fast(v0), tanh_fast(v1));
    }

    // ---- decode: d = gelu(Dec h2 + b) ; out = Ow d + ob ----
    float dv[5];
    #pragma unroll
    for (int j = 0; j < 5; j++){
        const u64* rd = reinterpret_cast<const u64*>(sDec + j*32);
        u64 acc = 0ull;
        #pragma unroll
        for (int c = 0; c < 16; c++) acc = fma2(rd[c], h2p[c], acc);
        dv[j] = gelu1(hadd2(acc) + sDecB[j]);
    }
    #pragma unroll
    for (int o = 0; o < 3; o++){
        float acc = sOb[o];
        #pragma unroll
        for (int j = 0; j < 5; j++) acc = fmaf(sOw[o*5 + j], dv[j], acc);
        out[r*3 + o] = acc;
    }
}

// ---------------- launch ----------------
extern "C" void kernel_launch(void* const* d_in, const int* in_sizes, int n_in,
                              void* d_out, int out_size)
{
    const float* x      = (const float*)d_in[0];
    const float* embw   = (const float*)d_in[1];
    const float* embb   = (const float*)d_in[2];
    const float* ipw    = (const float*)d_in[3];
    const float* ipb    = (const float*)d_in[4];
    const float* opw    = (const float*)d_in[5];
    const float* opb    = (const float*)d_in[6];
    const float* wih    = (const float*)d_in[7];
    const float* bih    = (const float*)d_in[8];
    const float* whh    = (const float*)d_in[9];
    const float* bhh    = (const float*)d_in[10];
    const float* decw   = (const float*)d_in[11];
    const float* decb   = (const float*)d_in[12];
    const float* outw   = (const float*)d_in[13];
    const float* outb   = (const float*)d_in[14];
    float* out = (float*)d_out;

    int B = in_sizes[0] / 10;

    prep_kernel<<<1, 1024>>>(ipw, ipb, opw, opb, wih, bih, bhh);

    int blocks = (B + 255) / 256;
    fused_kernel<<<blocks, 256>>>(x, embw, embb, whh, decw, decb, outw, outb, out, B);
}